// round 16
// baseline (speedup 1.0000x reference)
#include <cuda_runtime.h>
#include <stdint.h>

// TorchNeighborList on GB300 — R15 = R14 with rebalanced zero slices.
// Pure-zero crews run ~6.3TB/s, mixed idx+zero ~5.4, idx-alone ~4.5 — so
// shift zero bytes toward k1/k2 and shrink k4's tail.
//   k1: pass1 (role-interleaved) + zero [0, 15.625M) f4        (250MB)
//   k2: scanA + last-block scanB + zero [15.625M, 25.1875M)    (153MB, covers valid head)
//   k4: idx (x4 unroll) + zero [25.1875M, TWOP) + valid scatter (50MB tail)

#define NA    1024
#define PCI   523776            // NA*(NA-1)/2
#define MAXB  256
#define CUT   5.0f
#define OUTB  1664
#define CTRB  64
#define P1B   (OUTB + CTRB)     // 1728 pass1 roles
#define K1ZB  3456              // zero roles in k1
#define K1GRID (P1B + K1ZB)     // 5184
#define SCANAB 432
#define K2ZB  1024
#define NIB   3072              // idx blocks in k4
#define K4ZB  512               // zero blocks in k4
#define Z1    15625000          // k1 zero: [0, Z1) f4
#define Z2    25187500          // k2 zero: [Z1, Z2); k4 zero: [Z2, TWOP)

__device__ unsigned d_mask[442368];
__device__ int      d_wpre[442368];
__device__ int      d_bsums[512];
__device__ int      d_bpre[512];
__device__ int      d_atomCount[NA];
__device__ int      d_atomBase[NA];
__device__ unsigned d_bucket[NA * MAXB];
__device__ int      d_Vh;
__device__ int      d_V;
__device__ int      d_arrived;          // scanA completion counter

__device__ __forceinline__ int rowstartC(int i) {
    return i * 1023 - (i * (i - 1)) / 2;
}

__device__ __forceinline__ void decodeCenter(int t2, int& i0, int& j0) {
    float q = (float)t2;
    float disc = __fsub_rn(1047552.25f, __fadd_rn(q, q));
    int i = (int)(1023.5f - __fsqrt_rn(disc));
    if (i < 0) i = 0;
    if (i > 1022) i = 1022;
    while (rowstartC(i + 1) <= t2) ++i;
    while (rowstartC(i) > t2) --i;
    i0 = i;
    j0 = t2 - rowstartC(i) + i + 1;
}

__device__ __forceinline__ void zeroSlice(float4* p, int lo, int hi,
                                          int g, int stride) {
    float4 z = make_float4(0.f, 0.f, 0.f, 0.f);
    for (int i = lo + g; i < hi; i += stride)
        __stcs(&p[i], z);
}

// ---- K1: interleaved pass1 / zero-fill ----
__global__ void k1(const float* __restrict__ pos, const float* __restrict__ box,
                   const int* __restrict__ shifts, long long P, long long TWOP,
                   float* __restrict__ out) {
    __shared__ float spx[NA], spy[NA], spz[NA];
    int tid = threadIdx.x;
    int role = (int)(blockIdx.x % 3);
    if (role != 2) {
        int zid = (int)(blockIdx.x / 3) * 2 + role;
        int g = zid * 256 + tid;
        zeroSlice((float4*)(out + 2 * TWOP), 0, Z1, g, K1ZB * 256);
        return;
    }
    int pb = (int)(blockIdx.x / 3);     // pass1 block id in [0, P1B)
    for (int k = tid; k < NA; k += 256) {
        spx[k] = pos[3 * k + 0];
        spy[k] = pos[3 * k + 1];
        spz[k] = pos[3 * k + 2];
    }
    __syncthreads();
    if (pb < OUTB) {
        int rowBase = pb * 8;
        #pragma unroll 1
        for (int rr = 0; rr < 8; rr++) {
            int row = rowBase + rr;
            int s = row >> 10, i = row & 1023;
            float s0 = (float)shifts[3 * s + 0];
            float s1 = (float)shifts[3 * s + 1];
            float s2 = (float)shifts[3 * s + 2];
            float svx = s0 * box[0] + s1 * box[3] + s2 * box[6];
            float svy = s0 * box[1] + s1 * box[4] + s2 * box[7];
            float svz = s0 * box[2] + s1 * box[5] + s2 * box[8];
            float pix = spx[i], piy = spy[i], piz = spz[i];
            int t2base = PCI + (row << 10);
            #pragma unroll
            for (int c = 0; c < 4; c++) {
                int j = c * 256 + tid;
                float dx = __fadd_rn(__fsub_rn(pix, spx[j]), svx);
                float dy = __fadd_rn(__fsub_rn(piy, spy[j]), svy);
                float dz = __fadd_rn(__fsub_rn(piz, spz[j]), svz);
                float r2 = __fadd_rn(__fadd_rn(__fmul_rn(dx, dx), __fmul_rn(dy, dy)),
                                     __fmul_rn(dz, dz));
                bool valid = __fsqrt_rn(r2) < CUT;
                unsigned b = __ballot_sync(0xFFFFFFFFu, valid);
                if ((tid & 31) == 0)
                    d_mask[(t2base >> 5) + c * 8 + (tid >> 5)] = b;
                if (valid) {
                    unsigned t2 = (unsigned)(t2base + j);
                    int sl = atomicAdd(&d_atomCount[i], 1);
                    if (sl < MAXB) d_bucket[i * MAXB + sl] = t2;
                    int s2a = atomicAdd(&d_atomCount[j], 1);
                    if (s2a < MAXB) d_bucket[j * MAXB + s2a] = t2 + (unsigned)P;
                }
            }
        }
    } else {
        int cb = pb - OUTB;
        #pragma unroll 1
        for (int c = 0; c < 32; c++) {
            int t2 = cb * 8192 + c * 256 + tid;
            bool valid = false;
            int i0 = 0, j0 = 0;
            if (t2 < PCI) {
                decodeCenter(t2, i0, j0);
                float dx = __fsub_rn(spx[i0], spx[j0]);
                float dy = __fsub_rn(spy[i0], spy[j0]);
                float dz = __fsub_rn(spz[i0], spz[j0]);
                float r2 = __fadd_rn(__fadd_rn(__fmul_rn(dx, dx), __fmul_rn(dy, dy)),
                                     __fmul_rn(dz, dz));
                valid = __fsqrt_rn(r2) < CUT;
            }
            unsigned b = __ballot_sync(0xFFFFFFFFu, valid);
            int wb = cb * 256 + c * 8 + (tid >> 5);
            if ((tid & 31) == 0 && wb < (PCI >> 5))
                d_mask[wb] = b;
            if (valid) {
                int sl = atomicAdd(&d_atomCount[i0], 1);
                if (sl < MAXB) d_bucket[i0 * MAXB + sl] = (unsigned)t2;
                int s2a = atomicAdd(&d_atomCount[j0], 1);
                if (s2a < MAXB) d_bucket[j0 * MAXB + s2a] = (unsigned)(t2 + P);
            }
        }
    }
}

// ---- K2: scanA + last-block scanB + zero slice [Z1, Z2) ----
__global__ void k2(int W, long long TWOP, float* __restrict__ out) {
    if (blockIdx.x >= SCANAB) {
        int g = (blockIdx.x - SCANAB) * 1024 + threadIdx.x;
        zeroSlice((float4*)(out + 2 * TWOP), Z1, Z2, g, K2ZB * 1024);
        return;
    }
    __shared__ int wsum[32];
    __shared__ int sLast;
    int tid = threadIdx.x, lane = tid & 31, wid = tid >> 5;
    int w = blockIdx.x * 1024 + tid;
    int v = (w < W) ? __popc(d_mask[w]) : 0;
    int x = v;
    #pragma unroll
    for (int o = 1; o < 32; o <<= 1) {
        int y = __shfl_up_sync(0xFFFFFFFFu, x, o);
        if (lane >= o) x += y;
    }
    if (lane == 31) wsum[wid] = x;
    __syncthreads();
    if (wid == 0) {
        int y = wsum[lane];
        #pragma unroll
        for (int o = 1; o < 32; o <<= 1) {
            int z = __shfl_up_sync(0xFFFFFFFFu, y, o);
            if (lane >= o) y += z;
        }
        wsum[lane] = y;
    }
    __syncthreads();
    int base = wid ? wsum[wid - 1] : 0;
    if (w < W) d_wpre[w] = base + x - v;
    if (tid == 0) {
        d_bsums[blockIdx.x] = wsum[31];
        __threadfence();
        int n = atomicAdd(&d_arrived, 1);
        sLast = (n == SCANAB - 1) ? 1 : 0;
    }
    __syncthreads();
    if (!sLast) return;

    // ---- last block: scanB over block sums + atom scan ----
    int vb = (tid < SCANAB) ? *((volatile int*)&d_bsums[tid]) : 0;
    int xb = vb;
    #pragma unroll
    for (int o = 1; o < 32; o <<= 1) {
        int y = __shfl_up_sync(0xFFFFFFFFu, xb, o);
        if (lane >= o) xb += y;
    }
    __syncthreads();
    if (lane == 31) wsum[wid] = xb;
    __syncthreads();
    if (wid == 0) {
        int y = wsum[lane];
        #pragma unroll
        for (int o = 1; o < 32; o <<= 1) {
            int z = __shfl_up_sync(0xFFFFFFFFu, y, o);
            if (lane >= o) y += z;
        }
        wsum[lane] = y;
    }
    __syncthreads();
    int baseb = wid ? wsum[wid - 1] : 0;
    if (tid < SCANAB) d_bpre[tid] = baseb + xb - vb;
    if (tid == 0) {
        d_Vh = wsum[31];
        d_V = 2 * wsum[31];
        d_arrived = 0;          // reset for next graph replay
    }
    __syncthreads();
    int a = *((volatile int*)&d_atomCount[tid]);
    int xa = a;
    #pragma unroll
    for (int o = 1; o < 32; o <<= 1) {
        int y = __shfl_up_sync(0xFFFFFFFFu, xa, o);
        if (lane >= o) xa += y;
    }
    __syncthreads();
    if (lane == 31) wsum[wid] = xa;
    __syncthreads();
    if (wid == 0) {
        int y = wsum[lane];
        #pragma unroll
        for (int o = 1; o < 32; o <<= 1) {
            int z = __shfl_up_sync(0xFFFFFFFFu, y, o);
            if (lane >= o) y += z;
        }
        wsum[lane] = y;
    }
    __syncthreads();
    int basea = wid ? wsum[wid - 1] : 0;
    d_atomBase[tid] = basea + xa - a;
    __threadfence();
}

// ---- K4: idx writer (x4 unroll batched loads) | zero [Z2,TWOP) | valid ----
__global__ void k4(const float* __restrict__ box, const int* __restrict__ shifts,
                   long long P64, long long TWOP64, float* __restrict__ out) {
    __shared__ unsigned sb[MAXB];
    int b = blockIdx.x, tid = threadIdx.x;
    int P = (int)P64, TWOP = (int)TWOP64;
    if (b < NIB) {
        int V = d_V, Vh = d_Vh;
        int roff = P - Vh;
        const int S = NIB * 256;
        int base = b * 256 + tid;
        for (int tl0 = base; tl0 < P; tl0 += 4 * S) {
            unsigned wordv[4];
            int prev[4];
            #pragma unroll
            for (int e = 0; e < 4; e++) {
                int tl = tl0 + e * S;
                if (tl > P - 1) tl = P - 1;
                unsigned w = (unsigned)tl >> 5;
                wordv[e] = __ldg(&d_mask[w]);
                prev[e] = __ldg(&d_bpre[w >> 10]) + __ldg(&d_wpre[w]);
            }
            #pragma unroll
            for (int e = 0; e < 4; e++) {
                int tl = tl0 + e * S;
                if (tl >= P) break;
                unsigned word = wordv[e];
                unsigned lanebit = 1u << (tl & 31);
                if (word & lanebit) continue;
                int before = prev[e] + __popc(word & (lanebit - 1u));
                int r1 = V + tl - before;
                int r2 = r1 + roff;
                int bi, bj;
                if (tl >= PCI) {
                    unsigned u = (unsigned)(tl - PCI);
                    bi = (int)((u >> 10) & 1023u);
                    bj = (int)(u & 1023u);
                } else {
                    decodeCenter(tl, bi, bj);
                }
                float fbi = (float)bi, fbj = (float)bj;
                __stcs(&out[r1], fbi);
                __stcs(&out[TWOP + r1], fbj);
                __stcs(&out[r2], fbj);
                __stcs(&out[TWOP + r2], fbi);
            }
        }
    } else if (b < NIB + K4ZB) {
        int g = (b - NIB) * 256 + tid;
        zeroSlice((float4*)(out + 2 * TWOP64), Z2, TWOP, g, K4ZB * 256);
    } else {
        int v = b - NIB - K4ZB;
        int c = d_atomCount[v];
        if (c > MAXB) c = MAXB;
        for (int k = tid; k < c; k += 256) sb[k] = d_bucket[v * MAXB + k];
        __syncthreads();
        if (tid == 0) d_atomCount[v] = 0;   // reset for next graph replay
        if (tid >= c) return;
        unsigned te = sb[tid];
        int rank = 0;
        for (int k = 0; k < c; k++) rank += (sb[k] < te) ? 1 : 0;
        int r = d_atomBase[v] + rank;

        int t = (int)te;
        bool second = t >= P;
        int t2 = second ? t - P : t;
        int i0, j0, s;
        if (t2 >= PCI) {
            unsigned u = (unsigned)(t2 - PCI);
            s = (int)(u >> 20);
            i0 = (int)((u >> 10) & 1023u);
            j0 = (int)(u & 1023u);
        } else {
            s = -1;
            decodeCenter(t2, i0, j0);
        }
        int bi = second ? j0 : i0;
        int bj = second ? i0 : j0;
        float o0 = 0.f, o1 = 0.f, o2 = 0.f;
        if (s >= 0) {
            float sgn = second ? 1.0f : -1.0f;
            float s0 = sgn * (float)shifts[3 * s + 0];
            float s1 = sgn * (float)shifts[3 * s + 1];
            float s2 = sgn * (float)shifts[3 * s + 2];
            o0 = s0 * box[0] + s1 * box[3] + s2 * box[6];
            o1 = s0 * box[1] + s1 * box[4] + s2 * box[7];
            o2 = s0 * box[2] + s1 * box[5] + s2 * box[8];
        }
        out[r] = (float)bi;
        out[TWOP + r] = (float)bj;
        long long ob = 2LL * TWOP + 3LL * r;
        out[ob + 0] = o0;
        out[ob + 1] = o1;
        out[ob + 2] = o2;
        out[5LL * TWOP + r] = 1.0f;
    }
}

extern "C" void kernel_launch(void* const* d_in, const int* in_sizes, int n_in,
                              void* d_out, int out_size) {
    const float* pos  = (const float*)d_in[0];
    const float* box  = (const float*)d_in[1];
    const int* shifts = (const int*)d_in[2];

    long long TWOP = (long long)out_size / 6;    // 28,310,528
    long long P = TWOP / 2;                      // 14,155,264
    int W = (int)(P / 32);                       // 442,352
    float* out = (float*)d_out;

    k1<<<K1GRID, 256>>>(pos, box, shifts, P, TWOP, out);
    k2<<<SCANAB + K2ZB, 1024>>>(W, TWOP, out);
    k4<<<NIB + K4ZB + NA, 256>>>(box, shifts, P, TWOP, out);
}

// round 17
// speedup vs baseline: 1.0621x; 1.0621x over previous
#include <cuda_runtime.h>
#include <stdint.h>

// TorchNeighborList on GB300 — R16 = R14 + finer-grained pass1 (4 rows/block,
// 128 center blocks) with 1:1 parity interleave against zero-fill roles.
//   k1: pass1 + zero [0, 18.5M) f4
//   k2: scanA + last-block scanB + zero [18.5M, 23.5M)   (covers valid head)
//   k4: idx (x4 unroll batched loads) + zero [23.5M, TWOP) + valid scatter

#define NA    1024
#define PCI   523776            // NA*(NA-1)/2
#define MAXB  256
#define CUT   5.0f
#define OUTB  3328              // outside blocks, 4 rows each (13*1024/4)
#define CTRB  128               // center blocks, 4096 elems each
#define P1B   (OUTB + CTRB)     // 3456 pass1 roles
#define K1ZB  3456              // zero roles in k1
#define K1GRID (P1B + K1ZB)     // 6912
#define SCANAB 432
#define K2ZB  1024
#define NIB   3072              // idx blocks in k4
#define K4ZB  768               // zero blocks in k4
#define Z1    18500000          // k1 zero: [0, Z1) f4
#define Z2    23500000          // k2 zero: [Z1, Z2); k4 zero: [Z2, TWOP)

__device__ unsigned d_mask[442368];
__device__ int      d_wpre[442368];
__device__ int      d_bsums[512];
__device__ int      d_bpre[512];
__device__ int      d_atomCount[NA];
__device__ int      d_atomBase[NA];
__device__ unsigned d_bucket[NA * MAXB];
__device__ int      d_Vh;
__device__ int      d_V;
__device__ int      d_arrived;          // scanA completion counter

__device__ __forceinline__ int rowstartC(int i) {
    return i * 1023 - (i * (i - 1)) / 2;
}

__device__ __forceinline__ void decodeCenter(int t2, int& i0, int& j0) {
    float q = (float)t2;
    float disc = __fsub_rn(1047552.25f, __fadd_rn(q, q));
    int i = (int)(1023.5f - __fsqrt_rn(disc));
    if (i < 0) i = 0;
    if (i > 1022) i = 1022;
    while (rowstartC(i + 1) <= t2) ++i;
    while (rowstartC(i) > t2) --i;
    i0 = i;
    j0 = t2 - rowstartC(i) + i + 1;
}

__device__ __forceinline__ void zeroSlice(float4* p, int lo, int hi,
                                          int g, int stride) {
    float4 z = make_float4(0.f, 0.f, 0.f, 0.f);
    for (int i = lo + g; i < hi; i += stride)
        __stcs(&p[i], z);
}

// ---- K1: parity-interleaved pass1 / zero-fill ----
__global__ void k1(const float* __restrict__ pos, const float* __restrict__ box,
                   const int* __restrict__ shifts, long long P, long long TWOP,
                   float* __restrict__ out) {
    __shared__ float spx[NA], spy[NA], spz[NA];
    int tid = threadIdx.x;
    if ((blockIdx.x & 1) == 0) {
        int zid = (int)(blockIdx.x >> 1);
        int g = zid * 256 + tid;
        zeroSlice((float4*)(out + 2 * TWOP), 0, Z1, g, K1ZB * 256);
        return;
    }
    int pb = (int)(blockIdx.x >> 1);    // pass1 block id in [0, P1B)
    for (int k = tid; k < NA; k += 256) {
        spx[k] = pos[3 * k + 0];
        spy[k] = pos[3 * k + 1];
        spz[k] = pos[3 * k + 2];
    }
    __syncthreads();
    if (pb < OUTB) {
        int rowBase = pb * 4;
        #pragma unroll 1
        for (int rr = 0; rr < 4; rr++) {
            int row = rowBase + rr;
            int s = row >> 10, i = row & 1023;
            float s0 = (float)shifts[3 * s + 0];
            float s1 = (float)shifts[3 * s + 1];
            float s2 = (float)shifts[3 * s + 2];
            float svx = s0 * box[0] + s1 * box[3] + s2 * box[6];
            float svy = s0 * box[1] + s1 * box[4] + s2 * box[7];
            float svz = s0 * box[2] + s1 * box[5] + s2 * box[8];
            float pix = spx[i], piy = spy[i], piz = spz[i];
            int t2base = PCI + (row << 10);
            #pragma unroll
            for (int c = 0; c < 4; c++) {
                int j = c * 256 + tid;
                float dx = __fadd_rn(__fsub_rn(pix, spx[j]), svx);
                float dy = __fadd_rn(__fsub_rn(piy, spy[j]), svy);
                float dz = __fadd_rn(__fsub_rn(piz, spz[j]), svz);
                float r2 = __fadd_rn(__fadd_rn(__fmul_rn(dx, dx), __fmul_rn(dy, dy)),
                                     __fmul_rn(dz, dz));
                bool valid = __fsqrt_rn(r2) < CUT;
                unsigned b = __ballot_sync(0xFFFFFFFFu, valid);
                if ((tid & 31) == 0)
                    d_mask[(t2base >> 5) + c * 8 + (tid >> 5)] = b;
                if (valid) {
                    unsigned t2 = (unsigned)(t2base + j);
                    int sl = atomicAdd(&d_atomCount[i], 1);
                    if (sl < MAXB) d_bucket[i * MAXB + sl] = t2;
                    int s2a = atomicAdd(&d_atomCount[j], 1);
                    if (s2a < MAXB) d_bucket[j * MAXB + s2a] = t2 + (unsigned)P;
                }
            }
        }
    } else {
        int cb = pb - OUTB;
        #pragma unroll 1
        for (int c = 0; c < 16; c++) {
            int t2 = cb * 4096 + c * 256 + tid;
            bool valid = false;
            int i0 = 0, j0 = 0;
            if (t2 < PCI) {
                decodeCenter(t2, i0, j0);
                float dx = __fsub_rn(spx[i0], spx[j0]);
                float dy = __fsub_rn(spy[i0], spy[j0]);
                float dz = __fsub_rn(spz[i0], spz[j0]);
                float r2 = __fadd_rn(__fadd_rn(__fmul_rn(dx, dx), __fmul_rn(dy, dy)),
                                     __fmul_rn(dz, dz));
                valid = __fsqrt_rn(r2) < CUT;
            }
            unsigned b = __ballot_sync(0xFFFFFFFFu, valid);
            int wb = cb * 128 + c * 8 + (tid >> 5);
            if ((tid & 31) == 0 && wb < (PCI >> 5))
                d_mask[wb] = b;
            if (valid) {
                int sl = atomicAdd(&d_atomCount[i0], 1);
                if (sl < MAXB) d_bucket[i0 * MAXB + sl] = (unsigned)t2;
                int s2a = atomicAdd(&d_atomCount[j0], 1);
                if (s2a < MAXB) d_bucket[j0 * MAXB + s2a] = (unsigned)(t2 + P);
            }
        }
    }
}

// ---- K2: scanA + last-block scanB + zero slice [Z1, Z2) ----
__global__ void k2(int W, long long TWOP, float* __restrict__ out) {
    if (blockIdx.x >= SCANAB) {
        int g = (blockIdx.x - SCANAB) * 1024 + threadIdx.x;
        zeroSlice((float4*)(out + 2 * TWOP), Z1, Z2, g, K2ZB * 1024);
        return;
    }
    __shared__ int wsum[32];
    __shared__ int sLast;
    int tid = threadIdx.x, lane = tid & 31, wid = tid >> 5;
    int w = blockIdx.x * 1024 + tid;
    int v = (w < W) ? __popc(d_mask[w]) : 0;
    int x = v;
    #pragma unroll
    for (int o = 1; o < 32; o <<= 1) {
        int y = __shfl_up_sync(0xFFFFFFFFu, x, o);
        if (lane >= o) x += y;
    }
    if (lane == 31) wsum[wid] = x;
    __syncthreads();
    if (wid == 0) {
        int y = wsum[lane];
        #pragma unroll
        for (int o = 1; o < 32; o <<= 1) {
            int z = __shfl_up_sync(0xFFFFFFFFu, y, o);
            if (lane >= o) y += z;
        }
        wsum[lane] = y;
    }
    __syncthreads();
    int base = wid ? wsum[wid - 1] : 0;
    if (w < W) d_wpre[w] = base + x - v;
    if (tid == 0) {
        d_bsums[blockIdx.x] = wsum[31];
        __threadfence();
        int n = atomicAdd(&d_arrived, 1);
        sLast = (n == SCANAB - 1) ? 1 : 0;
    }
    __syncthreads();
    if (!sLast) return;

    // ---- last block: scanB over block sums + atom scan ----
    int vb = (tid < SCANAB) ? *((volatile int*)&d_bsums[tid]) : 0;
    int xb = vb;
    #pragma unroll
    for (int o = 1; o < 32; o <<= 1) {
        int y = __shfl_up_sync(0xFFFFFFFFu, xb, o);
        if (lane >= o) xb += y;
    }
    __syncthreads();
    if (lane == 31) wsum[wid] = xb;
    __syncthreads();
    if (wid == 0) {
        int y = wsum[lane];
        #pragma unroll
        for (int o = 1; o < 32; o <<= 1) {
            int z = __shfl_up_sync(0xFFFFFFFFu, y, o);
            if (lane >= o) y += z;
        }
        wsum[lane] = y;
    }
    __syncthreads();
    int baseb = wid ? wsum[wid - 1] : 0;
    if (tid < SCANAB) d_bpre[tid] = baseb + xb - vb;
    if (tid == 0) {
        d_Vh = wsum[31];
        d_V = 2 * wsum[31];
        d_arrived = 0;          // reset for next graph replay
    }
    __syncthreads();
    int a = *((volatile int*)&d_atomCount[tid]);
    int xa = a;
    #pragma unroll
    for (int o = 1; o < 32; o <<= 1) {
        int y = __shfl_up_sync(0xFFFFFFFFu, xa, o);
        if (lane >= o) xa += y;
    }
    __syncthreads();
    if (lane == 31) wsum[wid] = xa;
    __syncthreads();
    if (wid == 0) {
        int y = wsum[lane];
        #pragma unroll
        for (int o = 1; o < 32; o <<= 1) {
            int z = __shfl_up_sync(0xFFFFFFFFu, y, o);
            if (lane >= o) y += z;
        }
        wsum[lane] = y;
    }
    __syncthreads();
    int basea = wid ? wsum[wid - 1] : 0;
    d_atomBase[tid] = basea + xa - a;
    __threadfence();
}

// ---- K4: idx writer (x4 unroll batched loads) | zero [Z2,TWOP) | valid ----
__global__ void k4(const float* __restrict__ box, const int* __restrict__ shifts,
                   long long P64, long long TWOP64, float* __restrict__ out) {
    __shared__ unsigned sb[MAXB];
    int b = blockIdx.x, tid = threadIdx.x;
    int P = (int)P64, TWOP = (int)TWOP64;
    if (b < NIB) {
        int V = d_V, Vh = d_Vh;
        int roff = P - Vh;
        const int S = NIB * 256;
        int base = b * 256 + tid;
        for (int tl0 = base; tl0 < P; tl0 += 4 * S) {
            unsigned wordv[4];
            int prev[4];
            #pragma unroll
            for (int e = 0; e < 4; e++) {
                int tl = tl0 + e * S;
                if (tl > P - 1) tl = P - 1;
                unsigned w = (unsigned)tl >> 5;
                wordv[e] = __ldg(&d_mask[w]);
                prev[e] = __ldg(&d_bpre[w >> 10]) + __ldg(&d_wpre[w]);
            }
            #pragma unroll
            for (int e = 0; e < 4; e++) {
                int tl = tl0 + e * S;
                if (tl >= P) break;
                unsigned word = wordv[e];
                unsigned lanebit = 1u << (tl & 31);
                if (word & lanebit) continue;
                int before = prev[e] + __popc(word & (lanebit - 1u));
                int r1 = V + tl - before;
                int r2 = r1 + roff;
                int bi, bj;
                if (tl >= PCI) {
                    unsigned u = (unsigned)(tl - PCI);
                    bi = (int)((u >> 10) & 1023u);
                    bj = (int)(u & 1023u);
                } else {
                    decodeCenter(tl, bi, bj);
                }
                float fbi = (float)bi, fbj = (float)bj;
                __stcs(&out[r1], fbi);
                __stcs(&out[TWOP + r1], fbj);
                __stcs(&out[r2], fbj);
                __stcs(&out[TWOP + r2], fbi);
            }
        }
    } else if (b < NIB + K4ZB) {
        int g = (b - NIB) * 256 + tid;
        zeroSlice((float4*)(out + 2 * TWOP64), Z2, TWOP, g, K4ZB * 256);
    } else {
        int v = b - NIB - K4ZB;
        int c = d_atomCount[v];
        if (c > MAXB) c = MAXB;
        for (int k = tid; k < c; k += 256) sb[k] = d_bucket[v * MAXB + k];
        __syncthreads();
        if (tid == 0) d_atomCount[v] = 0;   // reset for next graph replay
        if (tid >= c) return;
        unsigned te = sb[tid];
        int rank = 0;
        for (int k = 0; k < c; k++) rank += (sb[k] < te) ? 1 : 0;
        int r = d_atomBase[v] + rank;

        int t = (int)te;
        bool second = t >= P;
        int t2 = second ? t - P : t;
        int i0, j0, s;
        if (t2 >= PCI) {
            unsigned u = (unsigned)(t2 - PCI);
            s = (int)(u >> 20);
            i0 = (int)((u >> 10) & 1023u);
            j0 = (int)(u & 1023u);
        } else {
            s = -1;
            decodeCenter(t2, i0, j0);
        }
        int bi = second ? j0 : i0;
        int bj = second ? i0 : j0;
        float o0 = 0.f, o1 = 0.f, o2 = 0.f;
        if (s >= 0) {
            float sgn = second ? 1.0f : -1.0f;
            float s0 = sgn * (float)shifts[3 * s + 0];
            float s1 = sgn * (float)shifts[3 * s + 1];
            float s2 = sgn * (float)shifts[3 * s + 2];
            o0 = s0 * box[0] + s1 * box[3] + s2 * box[6];
            o1 = s0 * box[1] + s1 * box[4] + s2 * box[7];
            o2 = s0 * box[2] + s1 * box[5] + s2 * box[8];
        }
        out[r] = (float)bi;
        out[TWOP + r] = (float)bj;
        long long ob = 2LL * TWOP + 3LL * r;
        out[ob + 0] = o0;
        out[ob + 1] = o1;
        out[ob + 2] = o2;
        out[5LL * TWOP + r] = 1.0f;
    }
}

extern "C" void kernel_launch(void* const* d_in, const int* in_sizes, int n_in,
                              void* d_out, int out_size) {
    const float* pos  = (const float*)d_in[0];
    const float* box  = (const float*)d_in[1];
    const int* shifts = (const int*)d_in[2];

    long long TWOP = (long long)out_size / 6;    // 28,310,528
    long long P = TWOP / 2;                      // 14,155,264
    int W = (int)(P / 32);                       // 442,352
    float* out = (float*)d_out;

    k1<<<K1GRID, 256>>>(pos, box, shifts, P, TWOP, out);
    k2<<<SCANAB + K2ZB, 1024>>>(W, TWOP, out);
    k4<<<NIB + K4ZB + NA, 256>>>(box, shifts, P, TWOP, out);
}